// round 1
// baseline (speedup 1.0000x reference)
#include <cuda_runtime.h>

#define EPSV 1e-5f
#define B_   16
#define T_   2048
#define TW   4

// ---------------- scratch (static device, no allocs) ----------------
__device__ __align__(128) float g_feats[B_*T_*16];
__device__ __align__(128) float g_pre[B_*T_*256];
__device__ __align__(128) float g_h[B_*T_*64];

// ---------------- CNN: per-window conv stack -> feats ----------------
// smem layout (floats):
//  w1s   [64*9]            = 576
//  w2s   [(c1*7+k)*32+c2]  = 14336
//  w3s   [(c2*5+k)*16+c3]  = 2560
//  s1,e1 [64]+[64]; s2,e2 [32]+[32]; s3,e3 [16]+[16]  = 224
//  win   [64]  (data at cols 4..53, zero margins)
//  o1    [64*64] (pos p at col p+4)
//  o2    [32*64] (pos p at col p+4)
//  o3    [16*56]
// total = 24800 floats = 99200 B
#define CNN_SMEM_FLOATS 24800

__global__ void __launch_bounds__(256) cnn_kernel(
    const float* __restrict__ x,
    const float* __restrict__ c1w, const float* __restrict__ c1b,
    const float* __restrict__ g1, const float* __restrict__ b1p,
    const float* __restrict__ m1, const float* __restrict__ v1,
    const float* __restrict__ c2w, const float* __restrict__ c2b,
    const float* __restrict__ g2, const float* __restrict__ b2p,
    const float* __restrict__ m2, const float* __restrict__ v2,
    const float* __restrict__ c3w, const float* __restrict__ c3b,
    const float* __restrict__ g3, const float* __restrict__ b3p,
    const float* __restrict__ m3, const float* __restrict__ v3)
{
    extern __shared__ float sm[];
    float* w1s = sm;             // 576
    float* w2s = sm + 576;       // 14336
    float* w3s = sm + 14912;     // 2560
    float* s1  = sm + 17472; float* e1 = s1 + 64;
    float* s2  = e1 + 64;    float* e2 = s2 + 32;
    float* s3  = e2 + 32;    float* e3 = s3 + 16;
    float* win = e3 + 16;    // 64
    float* o1  = win + 64;   // 4096
    float* o2  = o1 + 4096;  // 2048
    float* o3  = o2 + 2048;  // 896

    const int tid = threadIdx.x;

    // ---- weight staging (transposed layouts for conflict-free reads) ----
    for (int i = tid; i < 576; i += 256) w1s[i] = c1w[i];
    for (int i = tid; i < 14336; i += 256) {
        int c2 = i / 448; int r = i % 448; int c1 = r / 7; int k = r % 7;
        w2s[(c1*7 + k)*32 + c2] = c2w[i];
    }
    for (int i = tid; i < 2560; i += 256) {
        int c3 = i / 160; int r = i % 160; int cc = r / 5; int k = r % 5;
        w3s[(cc*5 + k)*16 + c3] = c3w[i];
    }
    // BN folded: y_eff = conv(x)*s + e
    if (tid < 64) {
        float s = g1[tid] * rsqrtf(v1[tid] + EPSV);
        s1[tid] = s; e1[tid] = (c1b[tid] - m1[tid]) * s + b1p[tid];
    } else if (tid < 96) {
        int c = tid - 64;
        float s = g2[c] * rsqrtf(v2[c] + EPSV);
        s2[c] = s; e2[c] = (c2b[c] - m2[c]) * s + b2p[c];
    } else if (tid < 112) {
        int c = tid - 96;
        float s = g3[c] * rsqrtf(v3[c] + EPSV);
        s3[c] = s; e3[c] = (c3b[c] - m3[c]) * s + b3p[c];
    }
    // zero win + o1 + o2 (contiguous) once; data cols rewritten per window
    for (int i = tid; i < 64 + 4096 + 2048; i += 256) win[i] = 0.f;
    __syncthreads();

    const int b  = blockIdx.y;
    const int t0 = blockIdx.x * TW;
    const float* xb = x + b * T_;

    for (int w = 0; w < TW; ++w) {
        const int t = t0 + w;
        if (tid < 50) {
            int idx = t - 49 + tid;
            win[tid + 4] = (idx >= 0) ? xb[idx] : 0.f;
        }
        __syncthreads();

        // ---- conv1: 64ch x 50pos, k=9, pad=4 ----
        for (int o = tid; o < 3200; o += 256) {
            int c = o / 50, p = o % 50;
            float acc = 0.f;
            #pragma unroll
            for (int k = 0; k < 9; ++k) acc += w1s[c*9 + k] * win[p + k];
            float v = acc * s1[c] + e1[c];
            o1[c*64 + p + 4] = v > 0.f ? v : 0.f;
        }
        __syncthreads();

        // ---- conv2: 32ch x 50pos, k=7, pad=3 (dominant) ----
        {
            int c2 = tid >> 3, pg = tid & 7, p0 = pg * 7;
            float acc[7];
            #pragma unroll
            for (int j = 0; j < 7; ++j) acc[j] = 0.f;
            for (int c1 = 0; c1 < 64; ++c1) {
                const float* row = o1 + c1*64 + p0 + 1;  // col(p0-3)=p0+1
                float v[13];
                #pragma unroll
                for (int i = 0; i < 13; ++i) v[i] = row[i];
                const float* wr = w2s + c1*7*32 + c2;
                #pragma unroll
                for (int k = 0; k < 7; ++k) {
                    float wv = wr[k*32];
                    #pragma unroll
                    for (int j = 0; j < 7; ++j) acc[j] += wv * v[k + j];
                }
            }
            float ss = s2[c2], bb = e2[c2];
            #pragma unroll
            for (int j = 0; j < 7; ++j) {
                int p = p0 + j;
                if (p < 50) {
                    float v = acc[j] * ss + bb;
                    o2[c2*64 + p + 4] = v > 0.f ? v : 0.f;
                }
            }
        }
        __syncthreads();

        // ---- conv3: 16ch x 50pos, k=5, pad=2 ----
        {
            int c3 = tid >> 4, pg = tid & 15, p0 = pg * 4;
            if (p0 < 50) {
                float acc[4] = {0.f, 0.f, 0.f, 0.f};
                for (int cc = 0; cc < 32; ++cc) {
                    const float* row = o2 + cc*64 + p0 + 2;  // col(p0-2)=p0+2
                    float v[8];
                    #pragma unroll
                    for (int i = 0; i < 8; ++i) v[i] = row[i];
                    const float* wr = w3s + cc*5*16 + c3;
                    #pragma unroll
                    for (int k = 0; k < 5; ++k) {
                        float wv = wr[k*16];
                        #pragma unroll
                        for (int j = 0; j < 4; ++j) acc[j] += wv * v[k + j];
                    }
                }
                float ss = s3[c3], bb = e3[c3];
                #pragma unroll
                for (int j = 0; j < 4; ++j) {
                    int p = p0 + j;
                    if (p < 50) {
                        float v = acc[j] * ss + bb;
                        o3[c3*56 + p] = v > 0.f ? v : 0.f;
                    }
                }
            }
        }
        __syncthreads();

        // ---- mean over 50 -> feats ----
        {
            int c3 = tid >> 4, l = tid & 15;
            float s = o3[c3*56 + l] + o3[c3*56 + l + 16] + o3[c3*56 + l + 32];
            if (l < 2) s += o3[c3*56 + l + 48];
            s += __shfl_down_sync(0xffffffffu, s, 8);
            s += __shfl_down_sync(0xffffffffu, s, 4);
            s += __shfl_down_sync(0xffffffffu, s, 2);
            s += __shfl_down_sync(0xffffffffu, s, 1);
            if (l == 0) g_feats[(b*T_ + t)*16 + c3] = s * 0.02f;
        }
        __syncthreads();
    }
}

// ---------------- pre-GEMMs ----------------
__global__ void __launch_bounds__(256) gemm_pre16(
    const float* __restrict__ wih, const float* __restrict__ bi, const float* __restrict__ bh)
{
    __shared__ float ws[16*256];
    __shared__ float ft[16*16];
    __shared__ float bs[256];
    int tid = threadIdx.x;
    for (int i = tid; i < 4096; i += 256) { int j = i >> 4, k = i & 15; ws[k*256 + j] = wih[i]; }
    bs[tid] = bi[tid] + bh[tid];
    int r0 = blockIdx.x * 16;
    ft[tid] = g_feats[r0*16 + tid];
    __syncthreads();
    float acc[16];
    #pragma unroll
    for (int r = 0; r < 16; ++r) acc[r] = bs[tid];
    #pragma unroll
    for (int k = 0; k < 16; ++k) {
        float w = ws[k*256 + tid];
        #pragma unroll
        for (int r = 0; r < 16; ++r) acc[r] += w * ft[r*16 + k];
    }
    #pragma unroll
    for (int r = 0; r < 16; ++r) g_pre[(r0 + r)*256 + tid] = acc[r];
}

#define G64_SMEM_FLOATS (16384 + 1024 + 256)
__global__ void __launch_bounds__(256) gemm_pre64(
    const float* __restrict__ wih, const float* __restrict__ bi, const float* __restrict__ bh)
{
    extern __shared__ float sm[];
    float* ws = sm;             // 64*256 (transposed)
    float* ht = sm + 16384;     // 16*64
    float* bs = ht + 1024;      // 256
    int tid = threadIdx.x;
    for (int i = tid; i < 16384; i += 256) { int j = i >> 6, k = i & 63; ws[k*256 + j] = wih[i]; }
    bs[tid] = bi[tid] + bh[tid];
    int r0 = blockIdx.x * 16;
    for (int i = tid; i < 1024; i += 256) ht[i] = g_h[r0*64 + i];
    __syncthreads();
    float acc[16];
    #pragma unroll
    for (int r = 0; r < 16; ++r) acc[r] = bs[tid];
    for (int k = 0; k < 64; ++k) {
        float w = ws[k*256 + tid];
        #pragma unroll
        for (int r = 0; r < 16; ++r) acc[r] += w * ht[r*64 + k];
    }
    #pragma unroll
    for (int r = 0; r < 16; ++r) g_pre[(r0 + r)*256 + tid] = acc[r];
}

// ---------------- LSTM recurrence ----------------
__device__ __forceinline__ float sigf(float x)  { return __fdividef(1.f, 1.f + __expf(-x)); }
__device__ __forceinline__ float tanhq(float x) { return __fdividef(2.f, 1.f + __expf(-2.f*x)) - 1.f; }

__global__ void __launch_bounds__(512) lstm_rec(const float* __restrict__ whh)
{
    const int b = blockIdx.x, tid = threadIdx.x;
    const int g = tid >> 1, half = tid & 1;
    __shared__ __align__(16) float hsm[64];
    __shared__ float gates[256];

    float4 wv[8];
    const float4* wrow = (const float4*)(whh + g*64 + half*32);
    #pragma unroll
    for (int q = 0; q < 8; ++q) wv[q] = wrow[q];

    if (tid < 64) hsm[tid] = 0.f;
    float c = 0.f;
    const float* preB = g_pre + (size_t)b * T_ * 256;
    float* hB = g_h + (size_t)b * T_ * 64;
    float pc = (half == 0) ? preB[g] : 0.f;
    __syncthreads();

    for (int t = 0; t < T_; ++t) {
        float pn = 0.f;
        if (half == 0 && t < T_ - 1) pn = preB[(t + 1)*256 + g];  // prefetch
        float acc = 0.f;
        const float4* h4 = ((const float4*)hsm) + half*8;
        #pragma unroll
        for (int q = 0; q < 8; ++q) {
            float4 hv = h4[q];
            acc += wv[q].x*hv.x + wv[q].y*hv.y + wv[q].z*hv.z + wv[q].w*hv.w;
        }
        acc += __shfl_xor_sync(0xffffffffu, acc, 1);
        if (half == 0) gates[g] = acc + pc;
        __syncthreads();
        if (tid < 64) {
            float gi = gates[tid], gf = gates[64 + tid], gg = gates[128 + tid], go = gates[192 + tid];
            c = sigf(gf)*c + sigf(gi)*tanhq(gg);
            float h = sigf(go)*tanhq(c);
            hsm[tid] = h;
            hB[t*64 + tid] = h;
        }
        __syncthreads();
        pc = pn;
    }
}

// ---------------- FC head ----------------
__global__ void __launch_bounds__(256) fc_kernel(
    const float* __restrict__ w1, const float* __restrict__ b1,
    const float* __restrict__ w2, const float* __restrict__ b2,
    float* __restrict__ out)
{
    __shared__ __align__(16) float w1s[2048];
    __shared__ float w2s[64];
    __shared__ float b1s[32];
    int tid = threadIdx.x;
    for (int i = tid; i < 2048; i += 256) w1s[i] = w1[i];
    if (tid < 64) w2s[tid] = w2[tid];
    if (tid < 32) b1s[tid] = b1[tid];
    __syncthreads();

    int gid = blockIdx.x*256 + tid;
    const float4* h4p = (const float4*)(g_h + (size_t)gid * 64);
    float4 h[16];
    #pragma unroll
    for (int q = 0; q < 16; ++q) h[q] = h4p[q];

    float l0 = b2[0], l1 = b2[1];
    #pragma unroll
    for (int i = 0; i < 32; ++i) {
        float acc = b1s[i];
        const float4* wr = (const float4*)(w1s + i*64);
        #pragma unroll
        for (int q = 0; q < 16; ++q) {
            float4 w4 = wr[q];
            acc += w4.x*h[q].x + w4.y*h[q].y + w4.z*h[q].z + w4.w*h[q].w;
        }
        acc = acc > 0.f ? acc : 0.f;
        l0 += w2s[i] * acc;
        l1 += w2s[32 + i] * acc;
    }
    ((float2*)out)[gid] = make_float2(l0, l1);
}

// ---------------- launch ----------------
extern "C" void kernel_launch(void* const* d_in, const int* in_sizes, int n_in,
                              void* d_out, int out_size)
{
    const float* x     = (const float*)d_in[0];
    const float* c1w   = (const float*)d_in[1];
    const float* c1b   = (const float*)d_in[2];
    const float* bn1g  = (const float*)d_in[3];
    const float* bn1b  = (const float*)d_in[4];
    const float* bn1m  = (const float*)d_in[5];
    const float* bn1v  = (const float*)d_in[6];
    const float* c2w   = (const float*)d_in[7];
    const float* c2b   = (const float*)d_in[8];
    const float* bn2g  = (const float*)d_in[9];
    const float* bn2b  = (const float*)d_in[10];
    const float* bn2m  = (const float*)d_in[11];
    const float* bn2v  = (const float*)d_in[12];
    const float* c3w   = (const float*)d_in[13];
    const float* c3b   = (const float*)d_in[14];
    const float* bn3g  = (const float*)d_in[15];
    const float* bn3b  = (const float*)d_in[16];
    const float* bn3m  = (const float*)d_in[17];
    const float* bn3v  = (const float*)d_in[18];
    const float* wih0  = (const float*)d_in[19];
    const float* whh0  = (const float*)d_in[20];
    const float* bih0  = (const float*)d_in[21];
    const float* bhh0  = (const float*)d_in[22];
    const float* wih1  = (const float*)d_in[23];
    const float* whh1  = (const float*)d_in[24];
    const float* bih1  = (const float*)d_in[25];
    const float* bhh1  = (const float*)d_in[26];
    const float* fc1w  = (const float*)d_in[27];
    const float* fc1b  = (const float*)d_in[28];
    const float* fc2w  = (const float*)d_in[29];
    const float* fc2b  = (const float*)d_in[30];

    cudaFuncSetAttribute(cnn_kernel, cudaFuncAttributeMaxDynamicSharedMemorySize,
                         CNN_SMEM_FLOATS * 4);
    cudaFuncSetAttribute(gemm_pre64, cudaFuncAttributeMaxDynamicSharedMemorySize,
                         G64_SMEM_FLOATS * 4);

    // 1) CNN -> feats
    cnn_kernel<<<dim3(T_ / TW, B_), 256, CNN_SMEM_FLOATS * 4>>>(
        x, c1w, c1b, bn1g, bn1b, bn1m, bn1v,
        c2w, c2b, bn2g, bn2b, bn2m, bn2v,
        c3w, c3b, bn3g, bn3b, bn3m, bn3v);

    // 2) pre0 = feats @ wih0^T + (bih0+bhh0)
    gemm_pre16<<<(B_ * T_) / 16, 256>>>(wih0, bih0, bhh0);

    // 3) LSTM layer 0 recurrence -> g_h = h1
    lstm_rec<<<B_, 512>>>(whh0);

    // 4) pre1 = h1 @ wih1^T + (bih1+bhh1)   (reuses g_pre)
    gemm_pre64<<<(B_ * T_) / 16, 256, G64_SMEM_FLOATS * 4>>>(wih1, bih1, bhh1);

    // 5) LSTM layer 1 recurrence -> g_h = h2 (overwrites h1)
    lstm_rec<<<B_, 512>>>(whh1);

    // 6) FC head -> logits
    fc_kernel<<<(B_ * T_) / 256, 256>>>(fc1w, fc1b, fc2w, fc2b, (float*)d_out);
}

// round 2
// speedup vs baseline: 1.1628x; 1.1628x over previous
#include <cuda_runtime.h>

#define EPSV 1e-5f
#define B_   16
#define T_   2048
#define S_   2112        // padded stride for global conv buffers
#define TWB  8           // windows per CTA in phase B

// ---------------- scratch (static device, no allocs) ----------------
__device__ __align__(128) float g_r1[B_*64*S_];   // global conv1 post-BN/ReLU, a in [0,2096]
__device__ __align__(128) float g_r2[B_*32*S_];   // global conv2, a in [7,2089]
__device__ __align__(128) float g_r3[B_*16*S_];   // global conv3, a in [9,2087]
__device__ __align__(128) float g_feats[B_*T_*16];
__device__ __align__(128) float g_pre[B_*T_*256];
__device__ __align__(128) float g_h[B_*T_*64];

// ======================= Phase A: global conv stack =======================
// XP[i] = (i>=49) ? x[i-49] : 0, i in [0,2096]  (49 left-pad zeros)

__global__ void __launch_bounds__(256) conv1g_kernel(
    const float* __restrict__ x,
    const float* __restrict__ c1w, const float* __restrict__ c1b,
    const float* __restrict__ g1, const float* __restrict__ b1p,
    const float* __restrict__ m1, const float* __restrict__ v1)
{
    __shared__ float xw[264];
    __shared__ float w1s[576];
    __shared__ float s1[64], e1[64];
    const int tid = threadIdx.x;
    const int b = blockIdx.y;
    const int a0 = blockIdx.x * 256;
    for (int u = tid; u < 264; u += 256) {
        int i = a0 - 4 + u;
        xw[u] = (i >= 49 && i < 2097) ? x[b*2048 + i - 49] : 0.f;
    }
    for (int i = tid; i < 576; i += 256) w1s[i] = c1w[i];
    if (tid < 64) {
        float s = g1[tid] * rsqrtf(v1[tid] + EPSV);
        s1[tid] = s; e1[tid] = (c1b[tid] - m1[tid]) * s + b1p[tid];
    }
    __syncthreads();
    int a = a0 + tid;
    if (a < 2097) {
        float xv[9];
        #pragma unroll
        for (int k = 0; k < 9; ++k) xv[k] = xw[tid + k];
        for (int c = 0; c < 64; ++c) {
            float acc = 0.f;
            #pragma unroll
            for (int k = 0; k < 9; ++k) acc += w1s[c*9 + k] * xv[k];
            float r = acc * s1[c] + e1[c];
            g_r1[(b*64 + c)*S_ + a] = r > 0.f ? r : 0.f;
        }
    }
}

#define C2G_SMEM_FLOATS (14336 + 64*72 + 64)
__global__ void __launch_bounds__(256) conv2g_kernel(
    const float* __restrict__ c2w, const float* __restrict__ c2b,
    const float* __restrict__ g2, const float* __restrict__ b2p,
    const float* __restrict__ m2, const float* __restrict__ v2)
{
    extern __shared__ float sm[];
    float* w2s = sm;               // [(c1*7+k)*32 + c2]
    float* r1t = sm + 14336;       // [64][72]
    float* s2  = r1t + 4608;
    float* e2  = s2 + 32;
    const int tid = threadIdx.x;
    const int b = blockIdx.y;
    const int a0 = 7 + blockIdx.x * 64;

    for (int i = tid; i < 14336; i += 256) {
        int c2 = i / 448; int r = i % 448; int c1 = r / 7; int k = r % 7;
        w2s[(c1*7 + k)*32 + c2] = c2w[i];
    }
    if (tid < 32) {
        float s = g2[tid] * rsqrtf(v2[tid] + EPSV);
        s2[tid] = s; e2[tid] = (c2b[tid] - m2[tid]) * s + b2p[tid];
    }
    for (int f = tid; f < 64*70; f += 256) {
        int c1 = f / 70, i = f - c1*70;
        int a = a0 - 3 + i;
        r1t[c1*72 + i] = (a <= 2096) ? g_r1[(b*64 + c1)*S_ + a] : 0.f;
    }
    __syncthreads();

    const int c2 = tid & 31, slot = tid >> 5;   // 8 slots x 8 positions
    float acc[8];
    #pragma unroll
    for (int j = 0; j < 8; ++j) acc[j] = 0.f;
    for (int c1 = 0; c1 < 64; ++c1) {
        const float* rp = r1t + c1*72 + slot*8;
        float v[14];
        #pragma unroll
        for (int i = 0; i < 14; ++i) v[i] = rp[i];
        const float* wp = w2s + c1*224 + c2;
        #pragma unroll
        for (int k = 0; k < 7; ++k) {
            float wv = wp[k*32];
            #pragma unroll
            for (int j = 0; j < 8; ++j) acc[j] += wv * v[k + j];
        }
    }
    float ss = s2[c2], bb = e2[c2];
    #pragma unroll
    for (int j = 0; j < 8; ++j) {
        int a = a0 + slot*8 + j;
        if (a <= 2089) {
            float r = acc[j] * ss + bb;
            g_r2[(b*32 + c2)*S_ + a] = r > 0.f ? r : 0.f;
        }
    }
}

__global__ void __launch_bounds__(256) conv3g_kernel(
    const float* __restrict__ c3w, const float* __restrict__ c3b,
    const float* __restrict__ g3, const float* __restrict__ b3p,
    const float* __restrict__ m3, const float* __restrict__ v3)
{
    __shared__ float w3s[2560];      // [(c2*5+k)*16 + c3]
    __shared__ float r2t[32*72];
    __shared__ float s3[16], e3[16];
    const int tid = threadIdx.x;
    const int b = blockIdx.y;
    const int a0 = 9 + blockIdx.x * 64;

    for (int i = tid; i < 2560; i += 256) {
        int c3 = i / 160; int r = i % 160; int cc = r / 5; int k = r % 5;
        w3s[(cc*5 + k)*16 + c3] = c3w[i];
    }
    if (tid < 16) {
        float s = g3[tid] * rsqrtf(v3[tid] + EPSV);
        s3[tid] = s; e3[tid] = (c3b[tid] - m3[tid]) * s + b3p[tid];
    }
    for (int f = tid; f < 32*68; f += 256) {
        int cc = f / 68, i = f - cc*68;
        int a = a0 - 2 + i;
        r2t[cc*72 + i] = (a <= 2089) ? g_r2[(b*32 + cc)*S_ + a] : 0.f;
    }
    __syncthreads();

    const int c3 = tid & 15, slot = tid >> 4;   // 16 slots x 4 positions
    float acc[4] = {0.f, 0.f, 0.f, 0.f};
    for (int cc = 0; cc < 32; ++cc) {
        const float* rp = r2t + cc*72 + slot*4;
        float v[8];
        #pragma unroll
        for (int i = 0; i < 8; ++i) v[i] = rp[i];
        const float* wp = w3s + cc*80 + c3;
        #pragma unroll
        for (int k = 0; k < 5; ++k) {
            float wv = wp[k*16];
            #pragma unroll
            for (int j = 0; j < 4; ++j) acc[j] += wv * v[k + j];
        }
    }
    float ss = s3[c3], bb = e3[c3];
    #pragma unroll
    for (int j = 0; j < 4; ++j) {
        int a = a0 + slot*4 + j;
        if (a <= 2087) {
            float r = acc[j] * ss + bb;
            g_r3[(b*16 + c3)*S_ + a] = r > 0.f ? r : 0.f;
        }
    }
}

// ======================= Phase B: per-window boundary =======================
// c1rows[c][32]: [0..2]=0, [3..12]=q0..9, [13..22]=q40..49, [23..25]=0
// c2rows[c][32]: [0..1]=0, [2..12]=q0..10, [13..23]=q39..49, [24..25]=0
// c3buf [c][20]: pi 0..8 = left p0..8, pi 9..17 = right p41..49
#define PB_SMEM_FLOATS 21104

__global__ void __launch_bounds__(256) boundary_kernel(
    const float* __restrict__ x,
    const float* __restrict__ c1w, const float* __restrict__ c1b,
    const float* __restrict__ g1, const float* __restrict__ b1p,
    const float* __restrict__ m1, const float* __restrict__ v1,
    const float* __restrict__ c2w, const float* __restrict__ c2b,
    const float* __restrict__ g2, const float* __restrict__ b2p,
    const float* __restrict__ m2, const float* __restrict__ v2,
    const float* __restrict__ c3w, const float* __restrict__ c3b,
    const float* __restrict__ g3, const float* __restrict__ b3p,
    const float* __restrict__ m3, const float* __restrict__ v3)
{
    extern __shared__ float sm[];
    float* w1s = sm;                 // 576
    float* w2s = sm + 576;           // 14336
    float* w3s = sm + 14912;         // 2560
    float* s1  = sm + 17472; float* e1 = s1 + 64;
    float* s2  = e1 + 64;    float* e2 = s2 + 32;
    float* s3  = e2 + 32;    float* e3 = s3 + 16;
    float* xwin   = e3 + 16;         // 16
    float* c1rows = xwin + 16;       // 2048
    float* c2rows = c1rows + 2048;   // 1024
    float* c3buf  = c2rows + 1024;   // 320

    const int tid = threadIdx.x;
    const int b = blockIdx.y;
    const int t0 = blockIdx.x * TWB;

    for (int i = tid; i < 576; i += 256) w1s[i] = c1w[i];
    for (int i = tid; i < 14336; i += 256) {
        int c2 = i / 448; int r = i % 448; int c1 = r / 7; int k = r % 7;
        w2s[(c1*7 + k)*32 + c2] = c2w[i];
    }
    for (int i = tid; i < 2560; i += 256) {
        int c3 = i / 160; int r = i % 160; int cc = r / 5; int k = r % 5;
        w3s[(cc*5 + k)*16 + c3] = c3w[i];
    }
    if (tid < 64) {
        float s = g1[tid] * rsqrtf(v1[tid] + EPSV);
        s1[tid] = s; e1[tid] = (c1b[tid] - m1[tid]) * s + b1p[tid];
    } else if (tid < 96) {
        int c = tid - 64;
        float s = g2[c] * rsqrtf(v2[c] + EPSV);
        s2[c] = s; e2[c] = (c2b[c] - m2[c]) * s + b2p[c];
    } else if (tid < 112) {
        int c = tid - 96;
        float s = g3[c] * rsqrtf(v3[c] + EPSV);
        s3[c] = s; e3[c] = (c3b[c] - m3[c]) * s + b3p[c];
    }
    // zero c1rows + c2rows (margins stay zero; data cols rewritten per window)
    for (int i = tid; i < 3072; i += 256) c1rows[i] = 0.f;
    __syncthreads();

    for (int w = 0; w < TWB; ++w) {
        const int t = t0 + w;

        // -- stage the 16 x values boundary conv1 needs --
        if (tid < 16) {
            int i = (tid < 8) ? (t + tid) : (t + 34 + tid);   // XP[t..t+7], XP[t+42..t+49]
            xwin[tid] = (i >= 49) ? x[b*2048 + i - 49] : 0.f;
        }
        __syncthreads();

        // -- conv1 window-specific: q in {0..3, 46..49}, 64 ch --
        #pragma unroll
        for (int r = 0; r < 2; ++r) {
            int o = tid + 256*r;               // 512 outputs
            int c = o >> 3, m = o & 7;
            float acc = 0.f;
            if (m < 4) {                       // left q = m, taps j = q-4+k in [-4,7]
                #pragma unroll
                for (int k = 0; k < 9; ++k) {
                    int j = m - 4 + k;
                    float xv = (j >= 0) ? xwin[j] : 0.f;
                    acc += w1s[c*9 + k] * xv;
                }
            } else {                           // right q = 42+m, taps j in [42,53]
                #pragma unroll
                for (int k = 0; k < 9; ++k) {
                    int j = 42 + m - 4 + k;
                    float xv = (j <= 49) ? xwin[8 + j - 42] : 0.f;
                    acc += w1s[c*9 + k] * xv;
                }
            }
            float rv = acc * s1[c] + e1[c];
            int q = (m < 4) ? m : (42 + m);
            int idx = (m < 4) ? (3 + q) : (13 + q - 40);
            c1rows[c*32 + idx] = rv > 0.f ? rv : 0.f;
        }
        // -- copy global R1 at q in {4..9, 40..45} --
        #pragma unroll
        for (int r = 0; r < 3; ++r) {
            int o = tid + 256*r;
            if (o < 768) {
                int c = o / 12, m = o - c*12;
                int q = (m < 6) ? (4 + m) : (34 + m);
                c1rows[c*32 + 7 + m] = g_r1[(b*64 + c)*S_ + t + q];
            }
        }
        // -- copy global R2 at q in {7..10, 39..42} --
        {
            int c2 = tid >> 3, m = tid & 7;
            int q = (m < 4) ? (7 + m) : (35 + m);
            c2rows[c2*32 + 9 + m] = g_r2[(b*32 + c2)*S_ + t + q];
        }
        __syncthreads();

        // -- conv2 window-specific: p in {0..6, 43..49}, 32 ch --
        {
            int c2 = tid & 31, j = tid >> 5;   // j 0..7, j==7 idle
            if (j < 7) {
                float accL = 0.f, accR = 0.f;
                for (int c1 = 0; c1 < 64; ++c1) {
                    const float* row = c1rows + c1*32;
                    float vl[7], vr[7];
                    #pragma unroll
                    for (int i = 0; i < 7; ++i) { vl[i] = row[j + i]; vr[i] = row[13 + j + i]; }
                    const float* wp = w2s + c1*224 + c2;
                    #pragma unroll
                    for (int k = 0; k < 7; ++k) {
                        float wv = wp[k*32];
                        accL += wv * vl[k];
                        accR += wv * vr[k];
                    }
                }
                float ss = s2[c2], bb = e2[c2];
                float rl = accL * ss + bb; rl = rl > 0.f ? rl : 0.f;
                float rr = accR * ss + bb; rr = rr > 0.f ? rr : 0.f;
                c2rows[c2*32 + 2 + j]  = rl;   // q' = j
                c2rows[c2*32 + 17 + j] = rr;   // q' = 43+j
            }
        }
        __syncthreads();

        // -- conv3 boundary: p in {0..8, 41..49}, 16 ch --
        {
            int c3 = tid & 15, slot = tid >> 4;
            #pragma unroll
            for (int rep = 0; rep < 2; ++rep) {
                int pi = slot + rep*16;
                if (pi < 18) {
                    int base = (pi < 9) ? pi : (4 + pi);   // left: p+k; right j=pi-9: 13+j+k
                    float acc = 0.f;
                    for (int cc = 0; cc < 32; ++cc) {
                        const float* row = c2rows + cc*32 + base;
                        const float* wp = w3s + cc*80 + c3;
                        #pragma unroll
                        for (int k = 0; k < 5; ++k) acc += wp[k*16] * row[k];
                    }
                    float rv = acc * s3[c3] + e3[c3];
                    c3buf[c3*20 + pi] = rv > 0.f ? rv : 0.f;
                }
            }
        }
        __syncthreads();

        // -- reduce: boundary 18 + interior 32 (global R3 at t+9..t+40), mean /50 --
        {
            int c = tid >> 4, l = tid & 15;
            float s = c3buf[c*20 + l];
            if (l < 2) s += c3buf[c*20 + 16 + l];
            const float* rp = g_r3 + (b*16 + c)*S_ + t + 9;
            s += rp[l] + rp[l + 16];
            s += __shfl_down_sync(0xffffffffu, s, 8, 16);
            s += __shfl_down_sync(0xffffffffu, s, 4, 16);
            s += __shfl_down_sync(0xffffffffu, s, 2, 16);
            s += __shfl_down_sync(0xffffffffu, s, 1, 16);
            if (l == 0) g_feats[(b*T_ + t)*16 + c] = s * 0.02f;
        }
        __syncthreads();
    }
}

// ---------------- pre-GEMMs ----------------
__global__ void __launch_bounds__(256) gemm_pre16(
    const float* __restrict__ wih, const float* __restrict__ bi, const float* __restrict__ bh)
{
    __shared__ float ws[16*256];
    __shared__ float ft[16*16];
    __shared__ float bs[256];
    int tid = threadIdx.x;
    for (int i = tid; i < 4096; i += 256) { int j = i >> 4, k = i & 15; ws[k*256 + j] = wih[i]; }
    bs[tid] = bi[tid] + bh[tid];
    int r0 = blockIdx.x * 16;
    ft[tid] = g_feats[r0*16 + tid];
    __syncthreads();
    float acc[16];
    #pragma unroll
    for (int r = 0; r < 16; ++r) acc[r] = bs[tid];
    #pragma unroll
    for (int k = 0; k < 16; ++k) {
        float w = ws[k*256 + tid];
        #pragma unroll
        for (int r = 0; r < 16; ++r) acc[r] += w * ft[r*16 + k];
    }
    #pragma unroll
    for (int r = 0; r < 16; ++r) g_pre[(r0 + r)*256 + tid] = acc[r];
}

#define G64_SMEM_FLOATS (16384 + 1024 + 256)
__global__ void __launch_bounds__(256) gemm_pre64(
    const float* __restrict__ wih, const float* __restrict__ bi, const float* __restrict__ bh)
{
    extern __shared__ float sm[];
    float* ws = sm;             // 64*256 (transposed)
    float* ht = sm + 16384;     // 16*64
    float* bs = ht + 1024;      // 256
    int tid = threadIdx.x;
    for (int i = tid; i < 16384; i += 256) { int j = i >> 6, k = i & 63; ws[k*256 + j] = wih[i]; }
    bs[tid] = bi[tid] + bh[tid];
    int r0 = blockIdx.x * 16;
    for (int i = tid; i < 1024; i += 256) ht[i] = g_h[r0*64 + i];
    __syncthreads();
    float acc[16];
    #pragma unroll
    for (int r = 0; r < 16; ++r) acc[r] = bs[tid];
    for (int k = 0; k < 64; ++k) {
        float w = ws[k*256 + tid];
        #pragma unroll
        for (int r = 0; r < 16; ++r) acc[r] += w * ht[r*64 + k];
    }
    #pragma unroll
    for (int r = 0; r < 16; ++r) g_pre[(r0 + r)*256 + tid] = acc[r];
}

// ---------------- LSTM recurrence ----------------
__device__ __forceinline__ float sigf(float x)  { return __fdividef(1.f, 1.f + __expf(-x)); }
__device__ __forceinline__ float tanhq(float x) { return __fdividef(2.f, 1.f + __expf(-2.f*x)) - 1.f; }

__global__ void __launch_bounds__(512) lstm_rec(const float* __restrict__ whh)
{
    const int b = blockIdx.x, tid = threadIdx.x;
    const int g = tid >> 1, half = tid & 1;
    __shared__ __align__(16) float hsm[64];
    __shared__ float gates[256];

    float4 wv[8];
    const float4* wrow = (const float4*)(whh + g*64 + half*32);
    #pragma unroll
    for (int q = 0; q < 8; ++q) wv[q] = wrow[q];

    if (tid < 64) hsm[tid] = 0.f;
    float c = 0.f;
    const float* preB = g_pre + (size_t)b * T_ * 256;
    float* hB = g_h + (size_t)b * T_ * 64;
    float pc = (half == 0) ? preB[g] : 0.f;
    __syncthreads();

    for (int t = 0; t < T_; ++t) {
        float pn = 0.f;
        if (half == 0 && t < T_ - 1) pn = preB[(t + 1)*256 + g];  // prefetch
        float acc = 0.f;
        const float4* h4 = ((const float4*)hsm) + half*8;
        #pragma unroll
        for (int q = 0; q < 8; ++q) {
            float4 hv = h4[q];
            acc += wv[q].x*hv.x + wv[q].y*hv.y + wv[q].z*hv.z + wv[q].w*hv.w;
        }
        acc += __shfl_xor_sync(0xffffffffu, acc, 1);
        if (half == 0) gates[g] = acc + pc;
        __syncthreads();
        if (tid < 64) {
            float gi = gates[tid], gf = gates[64 + tid], gg = gates[128 + tid], go = gates[192 + tid];
            c = sigf(gf)*c + sigf(gi)*tanhq(gg);
            float h = sigf(go)*tanhq(c);
            hsm[tid] = h;
            hB[t*64 + tid] = h;
        }
        __syncthreads();
        pc = pn;
    }
}

// ---------------- FC head ----------------
__global__ void __launch_bounds__(256) fc_kernel(
    const float* __restrict__ w1, const float* __restrict__ b1,
    const float* __restrict__ w2, const float* __restrict__ b2,
    float* __restrict__ out)
{
    __shared__ __align__(16) float w1s[2048];
    __shared__ float w2s[64];
    __shared__ float b1s[32];
    int tid = threadIdx.x;
    for (int i = tid; i < 2048; i += 256) w1s[i] = w1[i];
    if (tid < 64) w2s[tid] = w2[tid];
    if (tid < 32) b1s[tid] = b1[tid];
    __syncthreads();

    int gid = blockIdx.x*256 + tid;
    const float4* h4p = (const float4*)(g_h + (size_t)gid * 64);
    float4 h[16];
    #pragma unroll
    for (int q = 0; q < 16; ++q) h[q] = h4p[q];

    float l0 = b2[0], l1 = b2[1];
    #pragma unroll
    for (int i = 0; i < 32; ++i) {
        float acc = b1s[i];
        const float4* wr = (const float4*)(w1s + i*64);
        #pragma unroll
        for (int q = 0; q < 16; ++q) {
            float4 w4 = wr[q];
            acc += w4.x*h[q].x + w4.y*h[q].y + w4.z*h[q].z + w4.w*h[q].w;
        }
        acc = acc > 0.f ? acc : 0.f;
        l0 += w2s[i] * acc;
        l1 += w2s[32 + i] * acc;
    }
    ((float2*)out)[gid] = make_float2(l0, l1);
}

// ---------------- launch ----------------
extern "C" void kernel_launch(void* const* d_in, const int* in_sizes, int n_in,
                              void* d_out, int out_size)
{
    const float* x     = (const float*)d_in[0];
    const float* c1w   = (const float*)d_in[1];
    const float* c1b   = (const float*)d_in[2];
    const float* bn1g  = (const float*)d_in[3];
    const float* bn1b  = (const float*)d_in[4];
    const float* bn1m  = (const float*)d_in[5];
    const float* bn1v  = (const float*)d_in[6];
    const float* c2w   = (const float*)d_in[7];
    const float* c2b   = (const float*)d_in[8];
    const float* bn2g  = (const float*)d_in[9];
    const float* bn2b  = (const float*)d_in[10];
    const float* bn2m  = (const float*)d_in[11];
    const float* bn2v  = (const float*)d_in[12];
    const float* c3w   = (const float*)d_in[13];
    const float* c3b   = (const float*)d_in[14];
    const float* bn3g  = (const float*)d_in[15];
    const float* bn3b  = (const float*)d_in[16];
    const float* bn3m  = (const float*)d_in[17];
    const float* bn3v  = (const float*)d_in[18];
    const float* wih0  = (const float*)d_in[19];
    const float* whh0  = (const float*)d_in[20];
    const float* bih0  = (const float*)d_in[21];
    const float* bhh0  = (const float*)d_in[22];
    const float* wih1  = (const float*)d_in[23];
    const float* whh1  = (const float*)d_in[24];
    const float* bih1  = (const float*)d_in[25];
    const float* bhh1  = (const float*)d_in[26];
    const float* fc1w  = (const float*)d_in[27];
    const float* fc1b  = (const float*)d_in[28];
    const float* fc2w  = (const float*)d_in[29];
    const float* fc2b  = (const float*)d_in[30];

    cudaFuncSetAttribute(conv2g_kernel, cudaFuncAttributeMaxDynamicSharedMemorySize,
                         C2G_SMEM_FLOATS * 4);
    cudaFuncSetAttribute(boundary_kernel, cudaFuncAttributeMaxDynamicSharedMemorySize,
                         PB_SMEM_FLOATS * 4);
    cudaFuncSetAttribute(gemm_pre64, cudaFuncAttributeMaxDynamicSharedMemorySize,
                         G64_SMEM_FLOATS * 4);

    // Phase A: global conv stack
    conv1g_kernel<<<dim3(9, B_), 256>>>(x, c1w, c1b, bn1g, bn1b, bn1m, bn1v);
    conv2g_kernel<<<dim3(33, B_), 256, C2G_SMEM_FLOATS * 4>>>(c2w, c2b, bn2g, bn2b, bn2m, bn2v);
    conv3g_kernel<<<dim3(33, B_), 256>>>(c3w, c3b, bn3g, bn3b, bn3m, bn3v);

    // Phase B: per-window boundaries + mean -> feats
    boundary_kernel<<<dim3(T_ / TWB, B_), 256, PB_SMEM_FLOATS * 4>>>(
        x, c1w, c1b, bn1g, bn1b, bn1m, bn1v,
        c2w, c2b, bn2g, bn2b, bn2m, bn2v,
        c3w, c3b, bn3g, bn3b, bn3m, bn3v);

    // LSTM stack
    gemm_pre16<<<(B_ * T_) / 16, 256>>>(wih0, bih0, bhh0);
    lstm_rec<<<B_, 512>>>(whh0);
    gemm_pre64<<<(B_ * T_) / 16, 256, G64_SMEM_FLOATS * 4>>>(wih1, bih1, bhh1);
    lstm_rec<<<B_, 512>>>(whh1);

    // FC head
    fc_kernel<<<(B_ * T_) / 256, 256>>>(fc1w, fc1b, fc2w, fc2b, (float*)d_out);
}

// round 3
// speedup vs baseline: 1.4858x; 1.2778x over previous
#include <cuda_runtime.h>

#define EPSV 1e-5f
#define B_   16
#define T_   2048
#define S_   2112        // padded stride for global conv buffers

// Global buffers (index u):
//  g_r1 : conv1 post-ReLU at absolute pos a' = u-5,  u in [0,2106]
//  g_r2p: conv2 PRE-act   at absolute pos a  = u-2,  u in [0,2100]
//  g_r3p: conv3 PRE-act   at absolute pos a  = u,    u in [0,2096]
__device__ __align__(128) float g_r1 [B_*64*S_];
__device__ __align__(128) float g_r2p[B_*32*S_];
__device__ __align__(128) float g_r3p[B_*16*S_];
__device__ __align__(128) float g_D2 [B_*T_*2*7*32];   // conv2 window deltas (post-ReLU)
__device__ __align__(128) float g_feats[B_*T_*16];
__device__ __align__(128) float g_pre[B_*T_*256];
__device__ __align__(128) float g_h[B_*T_*64];

// ======================= Phase A: global conv stack =======================
// XP[i] = x[i-49] for 49<=i<=2096 else 0.

__global__ void __launch_bounds__(256) conv1g_kernel(
    const float* __restrict__ x,
    const float* __restrict__ c1w, const float* __restrict__ c1b,
    const float* __restrict__ g1, const float* __restrict__ b1p,
    const float* __restrict__ m1, const float* __restrict__ v1)
{
    __shared__ float xw[264];
    __shared__ float w1s[576];
    __shared__ float s1[64], e1[64];
    const int tid = threadIdx.x;
    const int b = blockIdx.y;
    const int u0 = blockIdx.x * 256;
    for (int j = tid; j < 264; j += 256) {
        int i = u0 - 9 + j;                      // XP index
        xw[j] = (i >= 49 && i <= 2096) ? x[b*2048 + i - 49] : 0.f;
    }
    for (int i = tid; i < 576; i += 256) w1s[i] = c1w[i];
    if (tid < 64) {
        float s = g1[tid] * rsqrtf(v1[tid] + EPSV);
        s1[tid] = s; e1[tid] = (c1b[tid] - m1[tid]) * s + b1p[tid];
    }
    __syncthreads();
    int u = u0 + tid;
    if (u < 2107) {
        float xv[9];
        #pragma unroll
        for (int k = 0; k < 9; ++k) xv[k] = xw[tid + k];
        for (int c = 0; c < 64; ++c) {
            float acc = 0.f;
            #pragma unroll
            for (int k = 0; k < 9; ++k) acc += w1s[c*9 + k] * xv[k];
            float r = acc * s1[c] + e1[c];
            g_r1[(b*64 + c)*S_ + u] = r > 0.f ? r : 0.f;
        }
    }
}

#define C2G_SMEM_FLOATS (14336 + 64*72 + 64)
__global__ void __launch_bounds__(256) conv2g_kernel(
    const float* __restrict__ c2w, const float* __restrict__ c2b,
    const float* __restrict__ g2, const float* __restrict__ b2p,
    const float* __restrict__ m2, const float* __restrict__ v2)
{
    extern __shared__ float sm[];
    float* w2s = sm;               // [(c1*7+k)*32 + c2]
    float* r1t = sm + 14336;       // [64][72]
    float* s2  = r1t + 4608;
    float* e2  = s2 + 32;
    const int tid = threadIdx.x;
    const int b = blockIdx.y;
    const int u0 = blockIdx.x * 64;

    for (int i = tid; i < 14336; i += 256) {
        int c2 = i / 448; int r = i % 448; int c1 = r / 7; int k = r % 7;
        w2s[(c1*7 + k)*32 + c2] = c2w[i];
    }
    if (tid < 32) {
        float s = g2[tid] * rsqrtf(v2[tid] + EPSV);
        s2[tid] = s; e2[tid] = (c2b[tid] - m2[tid]) * s + b2p[tid];
    }
    for (int f = tid; f < 64*70; f += 256) {
        int c1 = f / 70, i = f - c1*70;
        int u = u0 + i;
        r1t[c1*72 + i] = (u <= 2106) ? g_r1[(b*64 + c1)*S_ + u] : 0.f;
    }
    __syncthreads();

    const int c2 = tid & 31, slot = tid >> 5;   // 8 slots x 8 positions
    float acc[8];
    #pragma unroll
    for (int j = 0; j < 8; ++j) acc[j] = 0.f;
    for (int c1 = 0; c1 < 64; ++c1) {
        const float* rp = r1t + c1*72 + slot*8;
        float v[14];
        #pragma unroll
        for (int i = 0; i < 14; ++i) v[i] = rp[i];
        const float* wp = w2s + c1*224 + c2;
        #pragma unroll
        for (int k = 0; k < 7; ++k) {
            float wv = wp[k*32];
            #pragma unroll
            for (int j = 0; j < 8; ++j) acc[j] += wv * v[k + j];
        }
    }
    float ss = s2[c2], bb = e2[c2];
    #pragma unroll
    for (int j = 0; j < 8; ++j) {
        int u = u0 + slot*8 + j;
        if (u <= 2100)
            g_r2p[(b*32 + c2)*S_ + u] = acc[j] * ss + bb;   // PRE-act
    }
}

__global__ void __launch_bounds__(256) conv3g_kernel(
    const float* __restrict__ c3w, const float* __restrict__ c3b,
    const float* __restrict__ g3, const float* __restrict__ b3p,
    const float* __restrict__ m3, const float* __restrict__ v3)
{
    __shared__ float w3s[2560];      // [(c2*5+k)*16 + c3]
    __shared__ float r2t[32*72];
    __shared__ float s3[16], e3[16];
    const int tid = threadIdx.x;
    const int b = blockIdx.y;
    const int u0 = blockIdx.x * 64;

    for (int i = tid; i < 2560; i += 256) {
        int c3 = i / 160; int r = i % 160; int cc = r / 5; int k = r % 5;
        w3s[(cc*5 + k)*16 + c3] = c3w[i];
    }
    if (tid < 16) {
        float s = g3[tid] * rsqrtf(v3[tid] + EPSV);
        s3[tid] = s; e3[tid] = (c3b[tid] - m3[tid]) * s + b3p[tid];
    }
    for (int f = tid; f < 32*68; f += 256) {
        int cc = f / 68, i = f - cc*68;
        int u = u0 + i;
        float g = (u <= 2100) ? g_r2p[(b*32 + cc)*S_ + u] : 0.f;
        r2t[cc*72 + i] = g > 0.f ? g : 0.f;      // ReLU on load
    }
    __syncthreads();

    const int c3 = tid & 15, slot = tid >> 4;   // 16 slots x 4 positions
    float acc[4] = {0.f, 0.f, 0.f, 0.f};
    for (int cc = 0; cc < 32; ++cc) {
        const float* rp = r2t + cc*72 + slot*4;
        float v[8];
        #pragma unroll
        for (int i = 0; i < 8; ++i) v[i] = rp[i];
        const float* wp = w3s + cc*80 + c3;
        #pragma unroll
        for (int k = 0; k < 5; ++k) {
            float wv = wp[k*16];
            #pragma unroll
            for (int j = 0; j < 4; ++j) acc[j] += wv * v[k + j];
        }
    }
    float ss = s3[c3], bb = e3[c3];
    #pragma unroll
    for (int j = 0; j < 4; ++j) {
        int u = u0 + slot*4 + j;
        if (u <= 2096)
            g_r3p[(b*16 + c3)*S_ + u] = acc[j] * ss + bb;   // PRE-act
    }
}

// ======================= Phase B: batched boundary corrections =======================
// bnd2: thread = (w in 0..3, side, c2).  delta1 staged per (w,side,c1,qi<7) pad 8.
#define BND2_SMEM_FLOATS (14336 + 4096 + 32 + 32 + 64 + 64 + 32)

__global__ void __launch_bounds__(256) bnd2_kernel(
    const float* __restrict__ x,
    const float* __restrict__ c1w, const float* __restrict__ c1b,
    const float* __restrict__ g1, const float* __restrict__ b1p,
    const float* __restrict__ m1, const float* __restrict__ v1,
    const float* __restrict__ c2w,
    const float* __restrict__ g2, const float* __restrict__ v2)
{
    extern __shared__ float sm[];
    float* w2s    = sm;            // 14336  [(c1*7+k)*32 + c2]
    float* dstage = sm + 14336;    // 4096   [(w*2+side)*64 + c1][8]
    float* xsL    = dstage + 4096; // 32 = 4w x 8
    float* xsR    = xsL + 32;      // 32
    float* s1s    = xsR + 32;      // 64
    float* e1s    = s1s + 64;      // 64
    float* s2s    = e1s + 64;      // 32

    const int tid = threadIdx.x;
    const int b = blockIdx.y;
    const int t0 = blockIdx.x * 4;

    for (int i = tid; i < 14336; i += 256) {
        int c2 = i / 448; int r = i % 448; int c1 = r / 7; int k = r % 7;
        w2s[(c1*7 + k)*32 + c2] = c2w[i];
    }
    if (tid < 64) {
        float s = g1[tid] * rsqrtf(v1[tid] + EPSV);
        s1s[tid] = s; e1s[tid] = (c1b[tid] - m1[tid]) * s + b1p[tid];
    } else if (tid < 96) {
        int c = tid - 64;
        s2s[c] = g2[c] * rsqrtf(v2[c] + EPSV);
    } else if (tid < 160) {
        // xsL[w][j] = XP[t+j], xsR[w][j] = XP[t+42+j]
        int q = tid - 96;                 // 0..63
        int w = q >> 4, r = q & 15;
        int side = r >> 3, j = r & 7;
        int i = t0 + w + (side ? 42 + j : j);
        float v = (i >= 49 && i <= 2096) ? x[b*2048 + i - 49] : 0.f;
        (side ? xsR : xsL)[w*8 + j] = v;
    }
    __syncthreads();

    // -- stage delta1 --
    for (int s = tid; s < 4096; s += 256) {
        int qi = s & 7, c1 = (s >> 3) & 63, side = (s >> 9) & 1, w = s >> 10;
        int t = t0 + w;
        float val = 0.f;
        if (qi < 7) {
            if (side == 0) {
                float gl = g_r1[(b*64 + c1)*S_ + t + qi + 2];
                if (qi < 3) val = -gl;
                else {
                    int q = qi - 3;                     // window pos 0..3
                    float pre = 0.f;
                    const float* wp = c1w + c1*9;
                    #pragma unroll
                    for (int k = 0; k < 9; ++k)
                        if (k >= 4 - q) pre += __ldg(wp + k) * xsL[w*8 + q - 4 + k];
                    float rv = pre * s1s[c1] + e1s[c1];
                    val = (rv > 0.f ? rv : 0.f) - gl;
                }
            } else {
                float gl = g_r1[(b*64 + c1)*S_ + t + 51 + qi];
                if (qi >= 4) val = -gl;
                else {
                    int q = 46 + qi;                    // window pos 46..49
                    float pre = 0.f;
                    const float* wp = c1w + c1*9;
                    #pragma unroll
                    for (int k = 0; k < 9; ++k)
                        if (k <= 53 - q) pre += __ldg(wp + k) * xsR[w*8 + qi + k];
                    float rv = pre * s1s[c1] + e1s[c1];
                    val = (rv > 0.f ? rv : 0.f) - gl;
                }
            }
        }
        dstage[s] = val;
    }
    __syncthreads();

    // -- triangular correction: 28 (q,k) pairs per c1 per side --
    const int c2 = tid & 31, side = (tid >> 5) & 1, w = tid >> 6;
    const int t = t0 + w;
    float acc[7];
    #pragma unroll
    for (int p = 0; p < 7; ++p) acc[p] = 0.f;

    for (int c1 = 0; c1 < 64; ++c1) {
        const float* dp = dstage + ((w*2 + side)*64 + c1)*8;
        float4 A = *(const float4*)dp;
        float4 Bv = *(const float4*)(dp + 4);
        float d[8] = {A.x, A.y, A.z, A.w, Bv.x, Bv.y, Bv.z, Bv.w};
        const float* wp = w2s + c1*224 + c2;
        float wk[7];
        #pragma unroll
        for (int k = 0; k < 7; ++k) wk[k] = wp[k*32];
        if (side == 0) {
            #pragma unroll
            for (int p = 0; p < 7; ++p)
                #pragma unroll
                for (int k = 0; k < 7; ++k)
                    if (k + p <= 6) acc[p] += wk[k] * d[p + k];
        } else {
            #pragma unroll
            for (int p = 0; p < 7; ++p)
                #pragma unroll
                for (int k = 0; k < 7; ++k)
                    if (k >= 6 - p) acc[p] += wk[k] * d[p + k - 6];
        }
    }

    const float s2v = s2s[c2];
    const size_t btS = (size_t)(b*T_ + t)*2 + side;
    #pragma unroll
    for (int p = 0; p < 7; ++p) {
        int P = side ? 43 + p : p;
        float gpre = g_r2p[(b*32 + c2)*S_ + t + P + 2];
        float pre = gpre + s2v * acc[p];
        float d2 = (pre > 0.f ? pre : 0.f) - (gpre > 0.f ? gpre : 0.f);
        g_D2[(btS*7 + p)*32 + c2] = d2;
    }
}

// bnd3: thread = (w in 0..7, side, c3); one warp per window; feeds feats.
#define BND3_SMEM_FLOATS (2560 + 6144 + 16)
__global__ void __launch_bounds__(256) bnd3_kernel(
    const float* __restrict__ c3w,
    const float* __restrict__ g3, const float* __restrict__ v3)
{
    extern __shared__ float sm[];
    float* w3s   = sm;          // 2560  [c2*80 + k*16 + c3]
    float* stage = sm + 2560;   // 6144  [(w*2+side)*32 + c2][12]
    float* s3s   = stage + 6144;

    const int tid = threadIdx.x;
    const int b = blockIdx.y;
    const int t0 = blockIdx.x * 8;

    for (int i = tid; i < 2560; i += 256) {
        int c3 = i / 160; int r = i % 160; int cc = r / 5; int k = r % 5;
        w3s[(cc*5 + k)*16 + c3] = c3w[i];
    }
    if (tid < 16) s3s[tid] = g3[tid] * rsqrtf(v3[tid] + EPSV);

    for (int s = tid; s < 6144; s += 256) {
        int qi = s % 12; int r = s / 12;
        int c2 = r & 31, side = (r >> 5) & 1, w = r >> 6;
        int t = t0 + w;
        float val = 0.f;
        if (qi < 9) {
            size_t btS = (size_t)(b*T_ + t)*2 + side;
            if (side == 0) {
                if (qi < 2) {
                    float g = g_r2p[(b*32 + c2)*S_ + t + qi];
                    val = -(g > 0.f ? g : 0.f);
                } else val = g_D2[(btS*7 + qi - 2)*32 + c2];
            } else {
                if (qi < 7) val = g_D2[(btS*7 + qi)*32 + c2];
                else {
                    float g = g_r2p[(b*32 + c2)*S_ + t + 45 + qi];
                    val = -(g > 0.f ? g : 0.f);
                }
            }
        }
        stage[((w*2 + side)*32 + c2)*12 + qi] = val;
    }
    __syncthreads();

    const int c3 = tid & 15, side = (tid >> 4) & 1, w = tid >> 5;
    const int t = t0 + w;
    float acc[9];
    #pragma unroll
    for (int p = 0; p < 9; ++p) acc[p] = 0.f;

    for (int c2 = 0; c2 < 32; ++c2) {
        const float* dp = stage + ((w*2 + side)*32 + c2)*12;
        float4 A = *(const float4*)dp;
        float4 Bv = *(const float4*)(dp + 4);
        float4 C = *(const float4*)(dp + 8);
        float d[9] = {A.x, A.y, A.z, A.w, Bv.x, Bv.y, Bv.z, Bv.w, C.x};
        const float* wp = w3s + c2*80 + c3;
        float wk[5];
        #pragma unroll
        for (int k = 0; k < 5; ++k) wk[k] = wp[k*16];
        if (side == 0) {
            #pragma unroll
            for (int p = 0; p < 9; ++p)
                #pragma unroll
                for (int k = 0; k < 5; ++k)
                    if (p + k <= 8) acc[p] += wk[k] * d[p + k];
        } else {
            #pragma unroll
            for (int p = 0; p < 9; ++p)
                #pragma unroll
                for (int k = 0; k < 5; ++k)
                    if (k >= 4 - p) acc[p] += wk[k] * d[p + k - 4];
        }
    }

    float sum = 0.f;
    const float s3v = s3s[c3];
    const float* rp = g_r3p + (b*16 + c3)*S_ + t;
    #pragma unroll
    for (int j = 0; j < 9; ++j) {
        int P = side ? 41 + j : j;
        float pre = rp[P] + s3v * acc[j];
        sum += pre > 0.f ? pre : 0.f;
    }
    #pragma unroll
    for (int i = 0; i < 16; ++i) {
        float g = rp[9 + side*16 + i];
        sum += g > 0.f ? g : 0.f;
    }
    sum += __shfl_xor_sync(0xffffffffu, sum, 16);
    if (side == 0) g_feats[(b*T_ + t)*16 + c3] = sum * 0.02f;
}

// ---------------- pre-GEMMs ----------------
__global__ void __launch_bounds__(256) gemm_pre16(
    const float* __restrict__ wih, const float* __restrict__ bi, const float* __restrict__ bh)
{
    __shared__ float ws[16*256];
    __shared__ float ft[16*16];
    __shared__ float bs[256];
    int tid = threadIdx.x;
    for (int i = tid; i < 4096; i += 256) { int j = i >> 4, k = i & 15; ws[k*256 + j] = wih[i]; }
    bs[tid] = bi[tid] + bh[tid];
    int r0 = blockIdx.x * 16;
    ft[tid] = g_feats[r0*16 + tid];
    __syncthreads();
    float acc[16];
    #pragma unroll
    for (int r = 0; r < 16; ++r) acc[r] = bs[tid];
    #pragma unroll
    for (int k = 0; k < 16; ++k) {
        float w = ws[k*256 + tid];
        #pragma unroll
        for (int r = 0; r < 16; ++r) acc[r] += w * ft[r*16 + k];
    }
    #pragma unroll
    for (int r = 0; r < 16; ++r) g_pre[(r0 + r)*256 + tid] = acc[r];
}

#define G64_SMEM_FLOATS (16384 + 1024 + 256)
__global__ void __launch_bounds__(256) gemm_pre64(
    const float* __restrict__ wih, const float* __restrict__ bi, const float* __restrict__ bh)
{
    extern __shared__ float sm[];
    float* ws = sm;             // 64*256 (transposed)
    float* ht = sm + 16384;     // 16*64
    float* bs = ht + 1024;      // 256
    int tid = threadIdx.x;
    for (int i = tid; i < 16384; i += 256) { int j = i >> 6, k = i & 63; ws[k*256 + j] = wih[i]; }
    bs[tid] = bi[tid] + bh[tid];
    int r0 = blockIdx.x * 16;
    for (int i = tid; i < 1024; i += 256) ht[i] = g_h[r0*64 + i];
    __syncthreads();
    float acc[16];
    #pragma unroll
    for (int r = 0; r < 16; ++r) acc[r] = bs[tid];
    for (int k = 0; k < 64; ++k) {
        float w = ws[k*256 + tid];
        #pragma unroll
        for (int r = 0; r < 16; ++r) acc[r] += w * ht[r*64 + k];
    }
    #pragma unroll
    for (int r = 0; r < 16; ++r) g_pre[(r0 + r)*256 + tid] = acc[r];
}

// ---------------- LSTM recurrence ----------------
__device__ __forceinline__ float sigf(float x)  { return __fdividef(1.f, 1.f + __expf(-x)); }
__device__ __forceinline__ float tanhq(float x) { return __fdividef(2.f, 1.f + __expf(-2.f*x)) - 1.f; }

__global__ void __launch_bounds__(512) lstm_rec(const float* __restrict__ whh)
{
    const int b = blockIdx.x, tid = threadIdx.x;
    const int g = tid >> 1, half = tid & 1;
    __shared__ __align__(16) float hsm[64];
    __shared__ float gates[256];

    float4 wv[8];
    const float4* wrow = (const float4*)(whh + g*64 + half*32);
    #pragma unroll
    for (int q = 0; q < 8; ++q) wv[q] = wrow[q];

    if (tid < 64) hsm[tid] = 0.f;
    float c = 0.f;
    const float* preB = g_pre + (size_t)b * T_ * 256;
    float* hB = g_h + (size_t)b * T_ * 64;
    float pc = (half == 0) ? preB[g] : 0.f;
    __syncthreads();

    for (int t = 0; t < T_; ++t) {
        float pn = 0.f;
        if (half == 0 && t < T_ - 1) pn = preB[(t + 1)*256 + g];  // prefetch
        float acc = 0.f;
        const float4* h4 = ((const float4*)hsm) + half*8;
        #pragma unroll
        for (int q = 0; q < 8; ++q) {
            float4 hv = h4[q];
            acc += wv[q].x*hv.x + wv[q].y*hv.y + wv[q].z*hv.z + wv[q].w*hv.w;
        }
        acc += __shfl_xor_sync(0xffffffffu, acc, 1);
        if (half == 0) gates[g] = acc + pc;
        __syncthreads();
        if (tid < 64) {
            float gi = gates[tid], gf = gates[64 + tid], gg = gates[128 + tid], go = gates[192 + tid];
            c = sigf(gf)*c + sigf(gi)*tanhq(gg);
            float h = sigf(go)*tanhq(c);
            hsm[tid] = h;
            hB[t*64 + tid] = h;
        }
        __syncthreads();
        pc = pn;
    }
}

// ---------------- FC head ----------------
__global__ void __launch_bounds__(256) fc_kernel(
    const float* __restrict__ w1, const float* __restrict__ b1,
    const float* __restrict__ w2, const float* __restrict__ b2,
    float* __restrict__ out)
{
    __shared__ __align__(16) float w1s[2048];
    __shared__ float w2s[64];
    __shared__ float b1s[32];
    int tid = threadIdx.x;
    for (int i = tid; i < 2048; i += 256) w1s[i] = w1[i];
    if (tid < 64) w2s[tid] = w2[tid];
    if (tid < 32) b1s[tid] = b1[tid];
    __syncthreads();

    int gid = blockIdx.x*256 + tid;
    const float4* h4p = (const float4*)(g_h + (size_t)gid * 64);
    float4 h[16];
    #pragma unroll
    for (int q = 0; q < 16; ++q) h[q] = h4p[q];

    float l0 = b2[0], l1 = b2[1];
    #pragma unroll
    for (int i = 0; i < 32; ++i) {
        float acc = b1s[i];
        const float4* wr = (const float4*)(w1s + i*64);
        #pragma unroll
        for (int q = 0; q < 16; ++q) {
            float4 w4 = wr[q];
            acc += w4.x*h[q].x + w4.y*h[q].y + w4.z*h[q].z + w4.w*h[q].w;
        }
        acc = acc > 0.f ? acc : 0.f;
        l0 += w2s[i] * acc;
        l1 += w2s[32 + i] * acc;
    }
    ((float2*)out)[gid] = make_float2(l0, l1);
}

// ---------------- launch ----------------
extern "C" void kernel_launch(void* const* d_in, const int* in_sizes, int n_in,
                              void* d_out, int out_size)
{
    const float* x     = (const float*)d_in[0];
    const float* c1w   = (const float*)d_in[1];
    const float* c1b   = (const float*)d_in[2];
    const float* bn1g  = (const float*)d_in[3];
    const float* bn1b  = (const float*)d_in[4];
    const float* bn1m  = (const float*)d_in[5];
    const float* bn1v  = (const float*)d_in[6];
    const float* c2w   = (const float*)d_in[7];
    const float* c2b   = (const float*)d_in[8];
    const float* bn2g  = (const float*)d_in[9];
    const float* bn2b  = (const float*)d_in[10];
    const float* bn2m  = (const float*)d_in[11];
    const float* bn2v  = (const float*)d_in[12];
    const float* c3w   = (const float*)d_in[13];
    const float* c3b   = (const float*)d_in[14];
    const float* bn3g  = (const float*)d_in[15];
    const float* bn3b  = (const float*)d_in[16];
    const float* bn3m  = (const float*)d_in[17];
    const float* bn3v  = (const float*)d_in[18];
    const float* wih0  = (const float*)d_in[19];
    const float* whh0  = (const float*)d_in[20];
    const float* bih0  = (const float*)d_in[21];
    const float* bhh0  = (const float*)d_in[22];
    const float* wih1  = (const float*)d_in[23];
    const float* whh1  = (const float*)d_in[24];
    const float* bih1  = (const float*)d_in[25];
    const float* bhh1  = (const float*)d_in[26];
    const float* fc1w  = (const float*)d_in[27];
    const float* fc1b  = (const float*)d_in[28];
    const float* fc2w  = (const float*)d_in[29];
    const float* fc2b  = (const float*)d_in[30];

    cudaFuncSetAttribute(conv2g_kernel, cudaFuncAttributeMaxDynamicSharedMemorySize,
                         C2G_SMEM_FLOATS * 4);
    cudaFuncSetAttribute(bnd2_kernel, cudaFuncAttributeMaxDynamicSharedMemorySize,
                         BND2_SMEM_FLOATS * 4);
    cudaFuncSetAttribute(bnd3_kernel, cudaFuncAttributeMaxDynamicSharedMemorySize,
                         BND3_SMEM_FLOATS * 4);
    cudaFuncSetAttribute(gemm_pre64, cudaFuncAttributeMaxDynamicSharedMemorySize,
                         G64_SMEM_FLOATS * 4);

    // Phase A: global conv stack (extended ranges, pre-act for conv2/conv3)
    conv1g_kernel<<<dim3(9, B_), 256>>>(x, c1w, c1b, bn1g, bn1b, bn1m, bn1v);
    conv2g_kernel<<<dim3(33, B_), 256, C2G_SMEM_FLOATS * 4>>>(c2w, c2b, bn2g, bn2b, bn2m, bn2v);
    conv3g_kernel<<<dim3(33, B_), 256>>>(c3w, c3b, bn3g, bn3b, bn3m, bn3v);

    // Phase B: batched boundary corrections
    bnd2_kernel<<<dim3(T_/4, B_), 256, BND2_SMEM_FLOATS * 4>>>(
        x, c1w, c1b, bn1g, bn1b, bn1m, bn1v, c2w, bn2g, bn2v);
    bnd3_kernel<<<dim3(T_/8, B_), 256, BND3_SMEM_FLOATS * 4>>>(c3w, bn3g, bn3v);

    // LSTM stack
    gemm_pre16<<<(B_ * T_) / 16, 256>>>(wih0, bih0, bhh0);
    lstm_rec<<<B_, 512>>>(whh0);
    gemm_pre64<<<(B_ * T_) / 16, 256, G64_SMEM_FLOATS * 4>>>(wih1, bih1, bhh1);
    lstm_rec<<<B_, 512>>>(whh1);

    // FC head
    fc_kernel<<<(B_ * T_) / 256, 256>>>(fc1w, fc1b, fc2w, fc2b, (float*)d_out);
}

// round 4
// speedup vs baseline: 1.6695x; 1.1236x over previous
#include <cuda_runtime.h>

#define EPSV 1e-5f
#define B_   16
#define T_   2048
#define S_   2112        // padded stride for global conv buffers

// Global buffers:
//  g_r1 : [b][c1][u]  conv1 post-ReLU, abs pos a' = u-5,  u in [0,2106]
//  g_r2p: [b][u][32]  conv2 PRE-act,   abs pos a  = u-2,  u in [0,2100]
//  g_r3p: [b][u][16]  conv3 PRE-act,   abs pos a  = u,    u in [0,2096]
__device__ __align__(128) float g_r1 [B_*64*S_];
__device__ __align__(128) float g_r2p[B_*S_*32];
__device__ __align__(128) float g_r3p[B_*S_*16];
__device__ __align__(128) float g_feats[B_*T_*16];
__device__ __align__(128) float g_pre[B_*T_*256];
__device__ __align__(128) float g_h[B_*T_*64];

// ======================= Phase A: global conv stack =======================
// XP[i] = x[i-49] for 49<=i<=2096 else 0.

__global__ void __launch_bounds__(256) conv1g_kernel(
    const float* __restrict__ x,
    const float* __restrict__ c1w, const float* __restrict__ c1b,
    const float* __restrict__ g1, const float* __restrict__ b1p,
    const float* __restrict__ m1, const float* __restrict__ v1)
{
    __shared__ float xw[264];
    __shared__ float w1s[576];
    __shared__ float s1[64], e1[64];
    const int tid = threadIdx.x;
    const int b = blockIdx.y;
    const int u0 = blockIdx.x * 256;
    for (int j = tid; j < 264; j += 256) {
        int i = u0 - 9 + j;                      // XP index
        xw[j] = (i >= 49 && i <= 2096) ? x[b*2048 + i - 49] : 0.f;
    }
    for (int i = tid; i < 576; i += 256) w1s[i] = c1w[i];
    if (tid < 64) {
        float s = g1[tid] * rsqrtf(v1[tid] + EPSV);
        s1[tid] = s; e1[tid] = (c1b[tid] - m1[tid]) * s + b1p[tid];
    }
    __syncthreads();
    int u = u0 + tid;
    if (u < 2107) {
        float xv[9];
        #pragma unroll
        for (int k = 0; k < 9; ++k) xv[k] = xw[tid + k];
        for (int c = 0; c < 64; ++c) {
            float acc = 0.f;
            #pragma unroll
            for (int k = 0; k < 9; ++k) acc += w1s[c*9 + k] * xv[k];
            float r = acc * s1[c] + e1[c];
            g_r1[(b*64 + c)*S_ + u] = r > 0.f ? r : 0.f;
        }
    }
}

#define C2G_SMEM_FLOATS (14336 + 64*72 + 64)
__global__ void __launch_bounds__(256) conv2g_kernel(
    const float* __restrict__ c2w, const float* __restrict__ c2b,
    const float* __restrict__ g2, const float* __restrict__ b2p,
    const float* __restrict__ m2, const float* __restrict__ v2)
{
    extern __shared__ float sm[];
    float* w2s = sm;               // [(c1*7+k)*32 + c2]
    float* r1t = sm + 14336;       // [64][72]
    float* s2  = r1t + 4608;
    float* e2  = s2 + 32;
    const int tid = threadIdx.x;
    const int b = blockIdx.y;
    const int u0 = blockIdx.x * 64;

    for (int i = tid; i < 14336; i += 256) {
        int c2 = i / 448; int r = i % 448; int c1 = r / 7; int k = r % 7;
        w2s[(c1*7 + k)*32 + c2] = c2w[i];
    }
    if (tid < 32) {
        float s = g2[tid] * rsqrtf(v2[tid] + EPSV);
        s2[tid] = s; e2[tid] = (c2b[tid] - m2[tid]) * s + b2p[tid];
    }
    for (int f = tid; f < 64*70; f += 256) {
        int c1 = f / 70, i = f - c1*70;
        int u = u0 + i;
        r1t[c1*72 + i] = (u <= 2106) ? g_r1[(b*64 + c1)*S_ + u] : 0.f;
    }
    __syncthreads();

    const int c2 = tid & 31, slot = tid >> 5;   // 8 slots x 8 positions
    float acc[8];
    #pragma unroll
    for (int j = 0; j < 8; ++j) acc[j] = 0.f;
    for (int c1 = 0; c1 < 64; ++c1) {
        const float* rp = r1t + c1*72 + slot*8;
        float v[14];
        #pragma unroll
        for (int i = 0; i < 14; ++i) v[i] = rp[i];
        const float* wp = w2s + c1*224 + c2;
        #pragma unroll
        for (int k = 0; k < 7; ++k) {
            float wv = wp[k*32];
            #pragma unroll
            for (int j = 0; j < 8; ++j) acc[j] += wv * v[k + j];
        }
    }
    float ss = s2[c2], bb = e2[c2];
    #pragma unroll
    for (int j = 0; j < 8; ++j) {
        int u = u0 + slot*8 + j;
        if (u <= 2100)
            g_r2p[((size_t)b*S_ + u)*32 + c2] = acc[j] * ss + bb;   // PRE-act, chan-last
    }
}

__global__ void __launch_bounds__(256) conv3g_kernel(
    const float* __restrict__ c3w, const float* __restrict__ c3b,
    const float* __restrict__ g3, const float* __restrict__ b3p,
    const float* __restrict__ m3, const float* __restrict__ v3)
{
    __shared__ float w3s[2560];      // [(c2*5+k)*16 + c3]
    __shared__ float r2t[32*72];
    __shared__ float s3[16], e3[16];
    const int tid = threadIdx.x;
    const int b = blockIdx.y;
    const int u0 = blockIdx.x * 64;

    for (int i = tid; i < 2560; i += 256) {
        int c3 = i / 160; int r = i % 160; int cc = r / 5; int k = r % 5;
        w3s[(cc*5 + k)*16 + c3] = c3w[i];
    }
    if (tid < 16) {
        float s = g3[tid] * rsqrtf(v3[tid] + EPSV);
        s3[tid] = s; e3[tid] = (c3b[tid] - m3[tid]) * s + b3p[tid];
    }
    // coalesced: cc fastest
    for (int f = tid; f < 32*68; f += 256) {
        int cc = f & 31, i = f >> 5;
        int u = u0 + i;
        float g = (u <= 2100) ? g_r2p[((size_t)b*S_ + u)*32 + cc] : 0.f;
        r2t[cc*72 + i] = g > 0.f ? g : 0.f;      // ReLU on load
    }
    __syncthreads();

    const int c3 = tid & 15, slot = tid >> 4;   // 16 slots x 4 positions
    float acc[4] = {0.f, 0.f, 0.f, 0.f};
    for (int cc = 0; cc < 32; ++cc) {
        const float* rp = r2t + cc*72 + slot*4;
        float v[8];
        #pragma unroll
        for (int i = 0; i < 8; ++i) v[i] = rp[i];
        const float* wp = w3s + cc*80 + c3;
        #pragma unroll
        for (int k = 0; k < 5; ++k) {
            float wv = wp[k*16];
            #pragma unroll
            for (int j = 0; j < 4; ++j) acc[j] += wv * v[k + j];
        }
    }
    float ss = s3[c3], bb = e3[c3];
    #pragma unroll
    for (int j = 0; j < 4; ++j) {
        int u = u0 + slot*4 + j;
        if (u <= 2096)
            g_r3p[((size_t)b*S_ + u)*16 + c3] = acc[j] * ss + bb;   // PRE-act, chan-last
    }
}

// ======================= Phase B: persistent fused boundary kernel =======================
// smem layout (floats):
//  w2s    [14336]   [(c1*7+k)*32 + c2]
//  w3s    [2560]    [(c2*5+k)*16 + c3]
//  w1s    [576]
//  s1s[64] e1s[64] s2s[32] s3s[16]
//  xs     [64]      xsL = xs, xsR = xs+32  (per window 8 each)
//  dstage [4096]    [(w*2+side)*64 + c1][8]
//  stage3 [3072]    [(w*2+side)*32 + c2][12]
//  fbuf   [256]     [0..127]=boundary sums, [128..255]=interior sums
#define BND_SMEM_FLOATS (14336 + 2560 + 576 + 176 + 64 + 4096 + 3072 + 256)
#define NCTA  1024
#define NGRP  8

__global__ void __launch_bounds__(256, 2) bnd_fused_kernel(
    const float* __restrict__ x,
    const float* __restrict__ c1w, const float* __restrict__ c1b,
    const float* __restrict__ g1, const float* __restrict__ b1p,
    const float* __restrict__ m1, const float* __restrict__ v1,
    const float* __restrict__ c2w,
    const float* __restrict__ g2, const float* __restrict__ v2,
    const float* __restrict__ c3w,
    const float* __restrict__ g3, const float* __restrict__ v3)
{
    extern __shared__ float sm[];
    float* w2s    = sm;               // 14336
    float* w3s    = sm + 14336;       // 2560
    float* w1s    = sm + 16896;       // 576
    float* s1s    = sm + 17472;       // 64
    float* e1s    = sm + 17536;       // 64
    float* s2s    = sm + 17600;       // 32
    float* s3s    = sm + 17632;       // 16 (+pad to 17648)
    float* xs     = sm + 17648;       // 64
    float* dstage = sm + 17712;       // 4096
    float* stage3 = sm + 21808;       // 3072
    float* fbuf   = sm + 24880;       // 256

    const int tid = threadIdx.x;

    // ---- one-time staging ----
    for (int i = tid; i < 14336; i += 256) {
        int c2 = i / 448; int r = i % 448; int c1 = r / 7; int k = r % 7;
        w2s[(c1*7 + k)*32 + c2] = c2w[i];
    }
    for (int i = tid; i < 2560; i += 256) {
        int c3 = i / 160; int r = i % 160; int cc = r / 5; int k = r % 5;
        w3s[(cc*5 + k)*16 + c3] = c3w[i];
    }
    for (int i = tid; i < 576; i += 256) w1s[i] = c1w[i];
    if (tid < 64) {
        float s = g1[tid] * rsqrtf(v1[tid] + EPSV);
        s1s[tid] = s; e1s[tid] = (c1b[tid] - m1[tid]) * s + b1p[tid];
    } else if (tid < 96) {
        int c = tid - 64;
        s2s[c] = g2[c] * rsqrtf(v2[c] + EPSV);
    } else if (tid < 112) {
        int c = tid - 96;
        s3s[c] = g3[c] * rsqrtf(v3[c] + EPSV);
    }
    __syncthreads();

    for (int it = 0; it < NGRP; ++it) {
        const int gid = blockIdx.x * NGRP + it;
        const int b  = gid >> 9;                 // 512 groups per batch
        const int t0 = (gid & 511) * 4;

        // ---- 1) stage x values: xsL[w][j]=XP[t+j], xsR[w][j]=XP[t+42+j] ----
        if (tid < 64) {
            int w = tid >> 4, r = tid & 15;
            int side = r >> 3, j = r & 7;
            int i = t0 + w + (side ? 42 + j : j);
            float v = (i >= 49 && i <= 2096) ? x[b*2048 + i - 49] : 0.f;
            xs[side*32 + w*8 + j] = v;
        }
        __syncthreads();

        // ---- 2) stage delta1 ----
        for (int s = tid; s < 4096; s += 256) {
            int qi = s & 7, c1 = (s >> 3) & 63, side = (s >> 9) & 1, w = s >> 10;
            int t = t0 + w;
            float val = 0.f;
            if (qi < 7) {
                if (side == 0) {
                    float gl = g_r1[(b*64 + c1)*S_ + t + qi + 2];
                    if (qi < 3) val = -gl;
                    else {
                        int q = qi - 3;                 // window pos 0..3
                        float pre = 0.f;
                        #pragma unroll
                        for (int k = 0; k < 9; ++k)
                            if (k >= 4 - q) pre += w1s[c1*9 + k] * xs[w*8 + q - 4 + k];
                        float rv = pre * s1s[c1] + e1s[c1];
                        val = (rv > 0.f ? rv : 0.f) - gl;
                    }
                } else {
                    float gl = g_r1[(b*64 + c1)*S_ + t + 51 + qi];
                    if (qi >= 4) val = -gl;
                    else {
                        int q = 46 + qi;                // window pos 46..49
                        float pre = 0.f;
                        #pragma unroll
                        for (int k = 0; k < 9; ++k)
                            if (k <= 53 - q) pre += w1s[c1*9 + k] * xs[32 + w*8 + qi + k];
                        float rv = pre * s1s[c1] + e1s[c1];
                        val = (rv > 0.f ? rv : 0.f) - gl;
                    }
                }
            }
            dstage[s] = val;
        }
        __syncthreads();

        // ---- 3) conv2 correction -> stage3 (d2 + edges + zeros) ----
        {
            const int c2 = tid & 31, side = (tid >> 5) & 1, w = tid >> 6;
            const int t = t0 + w;
            float acc[7];
            #pragma unroll
            for (int p = 0; p < 7; ++p) acc[p] = 0.f;

            for (int c1 = 0; c1 < 64; ++c1) {
                const float* dp = dstage + ((w*2 + side)*64 + c1)*8;
                float4 A = *(const float4*)dp;
                float4 Bv = *(const float4*)(dp + 4);
                float d[8] = {A.x, A.y, A.z, A.w, Bv.x, Bv.y, Bv.z, Bv.w};
                const float* wp = w2s + c1*224 + c2;
                float wk[7];
                #pragma unroll
                for (int k = 0; k < 7; ++k) wk[k] = wp[k*32];
                if (side == 0) {
                    #pragma unroll
                    for (int p = 0; p < 7; ++p)
                        #pragma unroll
                        for (int k = 0; k < 7; ++k)
                            if (k + p <= 6) acc[p] += wk[k] * d[p + k];
                } else {
                    #pragma unroll
                    for (int p = 0; p < 7; ++p)
                        #pragma unroll
                        for (int k = 0; k < 7; ++k)
                            if (k >= 6 - p) acc[p] += wk[k] * d[p + k - 6];
                }
            }

            const float s2v = s2s[c2];
            float* sp = stage3 + ((w*2 + side)*32 + c2)*12;
            const float* gpb = g_r2p + ((size_t)b*S_ + t)*32 + c2;
            if (side == 0) {
                #pragma unroll
                for (int p = 0; p < 7; ++p) {
                    float gpre = gpb[(p + 2)*32];
                    float pre = gpre + s2v * acc[p];
                    sp[2 + p] = (pre > 0.f ? pre : 0.f) - (gpre > 0.f ? gpre : 0.f);
                }
                float e0 = gpb[0], e1v = gpb[32];
                sp[0] = -(e0 > 0.f ? e0 : 0.f);
                sp[1] = -(e1v > 0.f ? e1v : 0.f);
            } else {
                #pragma unroll
                for (int p = 0; p < 7; ++p) {
                    float gpre = gpb[(45 + p)*32];
                    float pre = gpre + s2v * acc[p];
                    sp[p] = (pre > 0.f ? pre : 0.f) - (gpre > 0.f ? gpre : 0.f);
                }
                float e0 = gpb[52*32], e1v = gpb[53*32];
                sp[7] = -(e0 > 0.f ? e0 : 0.f);
                sp[8] = -(e1v > 0.f ? e1v : 0.f);
            }
            sp[9] = 0.f; sp[10] = 0.f; sp[11] = 0.f;
        }
        __syncthreads();

        // ---- 4) conv3 correction (threads 0..127) + interior sums (128..255) ----
        if (tid < 128) {
            const int c3 = tid & 15, ws = tid >> 4;
            const int side = ws & 1, w = ws >> 1;
            const int t = t0 + w;
            float acc[9];
            #pragma unroll
            for (int p = 0; p < 9; ++p) acc[p] = 0.f;

            for (int c2 = 0; c2 < 32; ++c2) {
                const float* dp = stage3 + (ws*32 + c2)*12;
                float4 A = *(const float4*)dp;
                float4 Bv = *(const float4*)(dp + 4);
                float C = dp[8];
                float d[9] = {A.x, A.y, A.z, A.w, Bv.x, Bv.y, Bv.z, Bv.w, C};
                const float* wp = w3s + c2*80 + c3;
                float wk[5];
                #pragma unroll
                for (int k = 0; k < 5; ++k) wk[k] = wp[k*16];
                if (side == 0) {
                    #pragma unroll
                    for (int p = 0; p < 9; ++p)
                        #pragma unroll
                        for (int k = 0; k < 5; ++k)
                            if (p + k <= 8) acc[p] += wk[k] * d[p + k];
                } else {
                    #pragma unroll
                    for (int p = 0; p < 9; ++p)
                        #pragma unroll
                        for (int k = 0; k < 5; ++k)
                            if (k >= 4 - p) acc[p] += wk[k] * d[p + k - 4];
                }
            }

            float sum = 0.f;
            const float s3v = s3s[c3];
            const float* rp = g_r3p + ((size_t)b*S_ + t)*16 + c3;
            #pragma unroll
            for (int j = 0; j < 9; ++j) {
                int P = side ? 41 + j : j;
                float pre = rp[P*16] + s3v * acc[j];
                sum += pre > 0.f ? pre : 0.f;
            }
            fbuf[ws*16 + c3] = sum;
        } else {
            const int tt = tid - 128;
            const int c3 = tt & 15, ws = tt >> 4;
            const int side = ws & 1, w = ws >> 1;
            const int t = t0 + w;
            const float* rp = g_r3p + ((size_t)b*S_ + t + 9 + side*16)*16 + c3;
            float sum = 0.f;
            #pragma unroll
            for (int i = 0; i < 16; ++i) {
                float g = rp[i*16];
                sum += g > 0.f ? g : 0.f;
            }
            fbuf[128 + ws*16 + c3] = sum;
        }
        __syncthreads();

        // ---- 5) combine -> feats ----
        if (tid < 64) {
            int w = tid >> 4, c3 = tid & 15;
            float sum = fbuf[(w*2    )*16 + c3] + fbuf[(w*2 + 1)*16 + c3]
                      + fbuf[128 + (w*2)*16 + c3] + fbuf[128 + (w*2 + 1)*16 + c3];
            g_feats[(b*T_ + t0 + w)*16 + c3] = sum * 0.02f;
        }
        __syncthreads();
    }
}

// ---------------- pre-GEMMs ----------------
__global__ void __launch_bounds__(256) gemm_pre16(
    const float* __restrict__ wih, const float* __restrict__ bi, const float* __restrict__ bh)
{
    __shared__ float ws[16*256];
    __shared__ float ft[16*16];
    __shared__ float bs[256];
    int tid = threadIdx.x;
    for (int i = tid; i < 4096; i += 256) { int j = i >> 4, k = i & 15; ws[k*256 + j] = wih[i]; }
    bs[tid] = bi[tid] + bh[tid];
    int r0 = blockIdx.x * 16;
    ft[tid] = g_feats[r0*16 + tid];
    __syncthreads();
    float acc[16];
    #pragma unroll
    for (int r = 0; r < 16; ++r) acc[r] = bs[tid];
    #pragma unroll
    for (int k = 0; k < 16; ++k) {
        float w = ws[k*256 + tid];
        #pragma unroll
        for (int r = 0; r < 16; ++r) acc[r] += w * ft[r*16 + k];
    }
    #pragma unroll
    for (int r = 0; r < 16; ++r) g_pre[(r0 + r)*256 + tid] = acc[r];
}

#define G64_SMEM_FLOATS (16384 + 1024 + 256)
__global__ void __launch_bounds__(256) gemm_pre64(
    const float* __restrict__ wih, const float* __restrict__ bi, const float* __restrict__ bh)
{
    extern __shared__ float sm[];
    float* ws = sm;             // 64*256 (transposed)
    float* ht = sm + 16384;     // 16*64
    float* bs = ht + 1024;      // 256
    int tid = threadIdx.x;
    for (int i = tid; i < 16384; i += 256) { int j = i >> 6, k = i & 63; ws[k*256 + j] = wih[i]; }
    bs[tid] = bi[tid] + bh[tid];
    int r0 = blockIdx.x * 16;
    for (int i = tid; i < 1024; i += 256) ht[i] = g_h[r0*64 + i];
    __syncthreads();
    float acc[16];
    #pragma unroll
    for (int r = 0; r < 16; ++r) acc[r] = bs[tid];
    for (int k = 0; k < 64; ++k) {
        float w = ws[k*256 + tid];
        #pragma unroll
        for (int r = 0; r < 16; ++r) acc[r] += w * ht[r*64 + k];
    }
    #pragma unroll
    for (int r = 0; r < 16; ++r) g_pre[(r0 + r)*256 + tid] = acc[r];
}

// ---------------- LSTM recurrence ----------------
__device__ __forceinline__ float sigf(float x)  { return __fdividef(1.f, 1.f + __expf(-x)); }
__device__ __forceinline__ float tanhq(float x) { return __fdividef(2.f, 1.f + __expf(-2.f*x)) - 1.f; }

__global__ void __launch_bounds__(512) lstm_rec(const float* __restrict__ whh)
{
    const int b = blockIdx.x, tid = threadIdx.x;
    const int g = tid >> 1, half = tid & 1;
    __shared__ __align__(16) float hsm[64];
    __shared__ float gates[256];

    float4 wv[8];
    const float4* wrow = (const float4*)(whh + g*64 + half*32);
    #pragma unroll
    for (int q = 0; q < 8; ++q) wv[q] = wrow[q];

    if (tid < 64) hsm[tid] = 0.f;
    float c = 0.f;
    const float* preB = g_pre + (size_t)b * T_ * 256;
    float* hB = g_h + (size_t)b * T_ * 64;
    float pc = (half == 0) ? preB[g] : 0.f;
    __syncthreads();

    for (int t = 0; t < T_; ++t) {
        float pn = 0.f;
        if (half == 0 && t < T_ - 1) pn = preB[(t + 1)*256 + g];  // prefetch
        float acc = 0.f;
        const float4* h4 = ((const float4*)hsm) + half*8;
        #pragma unroll
        for (int q = 0; q < 8; ++q) {
            float4 hv = h4[q];
            acc += wv[q].x*hv.x + wv[q].y*hv.y + wv[q].z*hv.z + wv[q].w*hv.w;
        }
        acc += __shfl_xor_sync(0xffffffffu, acc, 1);
        if (half == 0) gates[g] = acc + pc;
        __syncthreads();
        if (tid < 64) {
            float gi = gates[tid], gf = gates[64 + tid], gg = gates[128 + tid], go = gates[192 + tid];
            c = sigf(gf)*c + sigf(gi)*tanhq(gg);
            float h = sigf(go)*tanhq(c);
            hsm[tid] = h;
            hB[t*64 + tid] = h;
        }
        __syncthreads();
        pc = pn;
    }
}

// ---------------- FC head ----------------
__global__ void __launch_bounds__(256) fc_kernel(
    const float* __restrict__ w1, const float* __restrict__ b1,
    const float* __restrict__ w2, const float* __restrict__ b2,
    float* __restrict__ out)
{
    __shared__ __align__(16) float w1s[2048];
    __shared__ float w2s[64];
    __shared__ float b1s[32];
    int tid = threadIdx.x;
    for (int i = tid; i < 2048; i += 256) w1s[i] = w1[i];
    if (tid < 64) w2s[tid] = w2[tid];
    if (tid < 32) b1s[tid] = b1[tid];
    __syncthreads();

    int gid = blockIdx.x*256 + tid;
    const float4* h4p = (const float4*)(g_h + (size_t)gid * 64);
    float4 h[16];
    #pragma unroll
    for (int q = 0; q < 16; ++q) h[q] = h4p[q];

    float l0 = b2[0], l1 = b2[1];
    #pragma unroll
    for (int i = 0; i < 32; ++i) {
        float acc = b1s[i];
        const float4* wr = (const float4*)(w1s + i*64);
        #pragma unroll
        for (int q = 0; q < 16; ++q) {
            float4 w4 = wr[q];
            acc += w4.x*h[q].x + w4.y*h[q].y + w4.z*h[q].z + w4.w*h[q].w;
        }
        acc = acc > 0.f ? acc : 0.f;
        l0 += w2s[i] * acc;
        l1 += w2s[32 + i] * acc;
    }
    ((float2*)out)[gid] = make_float2(l0, l1);
}

// ---------------- launch ----------------
extern "C" void kernel_launch(void* const* d_in, const int* in_sizes, int n_in,
                              void* d_out, int out_size)
{
    const float* x     = (const float*)d_in[0];
    const float* c1w   = (const float*)d_in[1];
    const float* c1b   = (const float*)d_in[2];
    const float* bn1g  = (const float*)d_in[3];
    const float* bn1b  = (const float*)d_in[4];
    const float* bn1m  = (const float*)d_in[5];
    const float* bn1v  = (const float*)d_in[6];
    const float* c2w   = (const float*)d_in[7];
    const float* c2b   = (const float*)d_in[8];
    const float* bn2g  = (const float*)d_in[9];
    const float* bn2b  = (const float*)d_in[10];
    const float* bn2m  = (const float*)d_in[11];
    const float* bn2v  = (const float*)d_in[12];
    const float* c3w   = (const float*)d_in[13];
    const float* c3b   = (const float*)d_in[14];
    const float* bn3g  = (const float*)d_in[15];
    const float* bn3b  = (const float*)d_in[16];
    const float* bn3m  = (const float*)d_in[17];
    const float* bn3v  = (const float*)d_in[18];
    const float* wih0  = (const float*)d_in[19];
    const float* whh0  = (const float*)d_in[20];
    const float* bih0  = (const float*)d_in[21];
    const float* bhh0  = (const float*)d_in[22];
    const float* wih1  = (const float*)d_in[23];
    const float* whh1  = (const float*)d_in[24];
    const float* bih1  = (const float*)d_in[25];
    const float* bhh1  = (const float*)d_in[26];
    const float* fc1w  = (const float*)d_in[27];
    const float* fc1b  = (const float*)d_in[28];
    const float* fc2w  = (const float*)d_in[29];
    const float* fc2b  = (const float*)d_in[30];

    cudaFuncSetAttribute(conv2g_kernel, cudaFuncAttributeMaxDynamicSharedMemorySize,
                         C2G_SMEM_FLOATS * 4);
    cudaFuncSetAttribute(bnd_fused_kernel, cudaFuncAttributeMaxDynamicSharedMemorySize,
                         BND_SMEM_FLOATS * 4);
    cudaFuncSetAttribute(gemm_pre64, cudaFuncAttributeMaxDynamicSharedMemorySize,
                         G64_SMEM_FLOATS * 4);

    // Phase A: global conv stack
    conv1g_kernel<<<dim3(9, B_), 256>>>(x, c1w, c1b, bn1g, bn1b, bn1m, bn1v);
    conv2g_kernel<<<dim3(33, B_), 256, C2G_SMEM_FLOATS * 4>>>(c2w, c2b, bn2g, bn2b, bn2m, bn2v);
    conv3g_kernel<<<dim3(33, B_), 256>>>(c3w, c3b, bn3g, bn3b, bn3m, bn3v);

    // Phase B: persistent fused boundary corrections -> feats
    bnd_fused_kernel<<<NCTA, 256, BND_SMEM_FLOATS * 4>>>(
        x, c1w, c1b, bn1g, bn1b, bn1m, bn1v,
        c2w, bn2g, bn2v, c3w, bn3g, bn3v);

    // LSTM stack
    gemm_pre16<<<(B_ * T_) / 16, 256>>>(wih0, bih0, bhh0);
    lstm_rec<<<B_, 512>>>(whh0);
    gemm_pre64<<<(B_ * T_) / 16, 256, G64_SMEM_FLOATS * 4>>>(wih1, bih1, bhh1);
    lstm_rec<<<B_, 512>>>(whh1);

    // FC head
    fc_kernel<<<(B_ * T_) / 256, 256>>>(fc1w, fc1b, fc2w, fc2b, (float*)d_out);
}